// round 11
// baseline (speedup 1.0000x reference)
#include <cuda_runtime.h>
#include <cstdint>

// MessagePassing: out[row[e]] += x[col[e]]  for e in [0, E)
// x: [N, 32] f32; edge_index: [2, E] int32. row = ei[0:E], col = ei[E:2E].
//
// Converged scatter (R1-R9): edge-parallel, 8 lanes/edge x 16B chunks, NC
// LDG.128 gather + red.global.add.v4.f32; at the ~6300 B/cyc LTS chip cap.
// R10's graph-level PDL cost 2us of launch overhead; this round fuses the
// zero pass and the scatter into ONE kernel with a device-side dependency:
//   blocks [0, ZB): zero out (4 float4/thread), fence, bump counter.
//   blocks [ZB, ..): gather prologue (x/ei only), spin on counter==ZB,
//                    then fire REDs.
// Zero blocks have the lowest bids -> dispatched first, never wait ->
// no deadlock. A 4-byte memset before the kernel resets the counter each
// graph replay (determinism).

#define D 32
#define U 4
#define ZVEC 4   // float4 stores per zero-block thread

__device__ unsigned g_zero_done;

__device__ __forceinline__ void red_add_v4(float* dst, float4 v) {
    asm volatile("red.global.add.v4.f32 [%0], {%1, %2, %3, %4};"
                 :: "l"(dst), "f"(v.x), "f"(v.y), "f"(v.z), "f"(v.w)
                 : "memory");
}

__global__ __launch_bounds__(256) void mp_fused_kernel(
        const float* __restrict__ x,
        const int* __restrict__ ei,
        float* __restrict__ out,
        int E, int ngroups, int n4, int ZB) {
    int bid = blockIdx.x;

    if (bid < ZB) {
        // ---- zero phase: block zeroes 256*ZVEC float4s ----
        float4 z = make_float4(0.f, 0.f, 0.f, 0.f);
        int base = bid * (256 * ZVEC) + threadIdx.x;
        #pragma unroll
        for (int i = 0; i < ZVEC; i++) {
            int idx = base + i * 256;
            if (idx < n4) reinterpret_cast<float4*>(out)[idx] = z;
        }
        __threadfence();
        __syncthreads();
        if (threadIdx.x == 0) atomicAdd(&g_zero_done, 1u);
        return;
    }

    // ---- scatter phase ----
    int t = (bid - ZB) * 256 + threadIdx.x;
    int g = t >> 3;                 // edge-group id: edges [g*U, g*U+U)
    int chunk = (t & 7) << 2;       // float offset within the 32-float row
    bool active = (g < ngroups);

    int r[U], c[U];
    float4 v[U];
    if (active) {
        int e0 = g * U;
        int4 rows = __ldg(reinterpret_cast<const int4*>(ei + e0));
        int4 cols = __ldg(reinterpret_cast<const int4*>(ei + E + e0));
        r[0] = rows.x; r[1] = rows.y; r[2] = rows.z; r[3] = rows.w;
        c[0] = cols.x; c[1] = cols.y; c[2] = cols.z; c[3] = cols.w;
        #pragma unroll
        for (int i = 0; i < U; i++)
            v[i] = __ldg(reinterpret_cast<const float4*>(
                       x + (long long)c[i] * D + chunk));
    }

    // wait until all zero blocks have published their stores
    if (threadIdx.x == 0) {
        unsigned done;
        do {
            asm volatile("ld.acquire.gpu.global.u32 %0, [%1];"
                         : "=r"(done) : "l"(&g_zero_done) : "memory");
        } while (done < (unsigned)ZB);
    }
    __syncthreads();

    if (active) {
        #pragma unroll
        for (int i = 0; i < U; i++)
            red_add_v4(out + (long long)r[i] * D + chunk, v[i]);
    }
}

// Scalar tail for E % U != 0 (not hit for E = 1.6M; kept for generality).
__global__ void mp_tail_kernel(const float* __restrict__ x,
                               const int* __restrict__ ei,
                               float* __restrict__ out,
                               int Estart, int E) {
    int t = blockIdx.x * blockDim.x + threadIdx.x;
    int e = Estart + (t >> 3);
    if (e >= E) return;
    int chunk = (t & 7) << 2;
    int r = ei[e];
    int c = ei[E + e];
    float4 v = __ldg(reinterpret_cast<const float4*>(
                   x + (long long)c * D + chunk));
    red_add_v4(out + (long long)r * D + chunk, v);
}

extern "C" void kernel_launch(void* const* d_in, const int* in_sizes, int n_in,
                              void* d_out, int out_size) {
    const float* x = (const float*)d_in[0];
    const int* ei = (const int*)d_in[1];
    float* out = (float*)d_out;

    const int E = in_sizes[1] / 2;    // edge_index has 2*E elements
    const int n4 = out_size / 4;      // out: N*32 floats -> N*8 float4

    // reset the zero-phase counter (captured as a memset node; replay-safe)
    void* ctr = nullptr;
    cudaGetSymbolAddress(&ctr, g_zero_done);
    cudaMemsetAsync(ctr, 0, sizeof(unsigned), 0);

    int ngroups = E / U;
    int ZB = (n4 + 256 * ZVEC - 1) / (256 * ZVEC);      // zero blocks
    int SB = (int)(((long long)ngroups * 8 + 255) / 256); // scatter blocks
    mp_fused_kernel<<<ZB + SB, 256>>>(x, ei, out, E, ngroups, n4, ZB);

    int tail = E - ngroups * U;
    if (tail > 0)
        mp_tail_kernel<<<(tail * 8 + 255) / 256, 256>>>(x, ei, out,
                                                        ngroups * U, E);
}